// round 1
// baseline (speedup 1.0000x reference)
#include <cuda_runtime.h>

// Problem dims
#define NB   4
#define NT   1024
#define NDM  1024
#define NH   16
#define NDK  64
#define NR   65      // 2*CLIP+1
#define NBH  64      // NB*NH

// ---------------------------------------------------------------------------
// Device scratch (allocation-free: static __device__ arrays)
// ---------------------------------------------------------------------------
__device__ __align__(16) float g_qW[NB * NH * NT * NDK];       // (B,H,T,Dk)
__device__ __align__(16) float g_kW[NB * NH * NT * NDK];
__device__ __align__(16) float g_vW[NB * NH * NT * NDK];
__device__ __align__(16) float g_biasQ[NB * NH * NT * NR];     // (B,H,T,65)
__device__ __align__(16) float g_heads[NB * NH * NT * NDK];    // (B,H,T,Dk)
__device__ __align__(16) float g_P[(size_t)NBH * NT * NT];     // (BH,T,T) probs

__device__ __forceinline__ int relidx(int delta) {
    delta = delta < -32 ? -32 : delta;
    delta = delta >  32 ?  32 : delta;
    return delta + 32;
}

// ---------------------------------------------------------------------------
// Kernel 1: projections  qW/kW/vW[b,h,t,d] = sum_m X[b,t,m] * W[h,m,d]
// Tiled SGEMM: M=4096 (b,t), N=64 per block (one head h), K=1024. BM=128,BN=64,BK=16.
// ---------------------------------------------------------------------------
template <int SEL>
__global__ void __launch_bounds__(256) proj_gemm(const float* __restrict__ X,
                                                 const float* __restrict__ W)
{
    __shared__ float As[16][128];
    __shared__ float Bs[16][64];
    float* out = (SEL == 0) ? g_qW : (SEL == 1) ? g_kW : g_vW;

    const int tid = threadIdx.x;
    const int m0  = blockIdx.y * 128;
    const int h   = blockIdx.x;                 // N-tile == one head
    const float* Wh = W + (size_t)h * NDM * NDK;

    const int ty  = tid >> 4, tx = tid & 15;
    const int lr  = tid >> 2;                   // A-load row 0..63
    const int lkq = (tid & 3) << 2;             // A-load k quad
    const int bkk = tid >> 4;                   // B-load k 0..15
    const int bkd = (tid & 15) << 2;            // B-load d quad

    float acc[8][4];
#pragma unroll
    for (int i = 0; i < 8; i++)
#pragma unroll
        for (int j = 0; j < 4; j++) acc[i][j] = 0.f;

    for (int k0 = 0; k0 < NDM; k0 += 16) {
#pragma unroll
        for (int rr = 0; rr < 128; rr += 64) {
            float4 v = *(const float4*)&X[(size_t)(m0 + lr + rr) * NDM + k0 + lkq];
            As[lkq + 0][lr + rr] = v.x;
            As[lkq + 1][lr + rr] = v.y;
            As[lkq + 2][lr + rr] = v.z;
            As[lkq + 3][lr + rr] = v.w;
        }
        *(float4*)&Bs[bkk][bkd] = *(const float4*)&Wh[(size_t)(k0 + bkk) * NDK + bkd];
        __syncthreads();
#pragma unroll
        for (int kk = 0; kk < 16; kk++) {
            float4 a0 = *(const float4*)&As[kk][ty * 8];
            float4 a1 = *(const float4*)&As[kk][ty * 8 + 4];
            float4 bv = *(const float4*)&Bs[kk][tx * 4];
            float a[8] = {a0.x, a0.y, a0.z, a0.w, a1.x, a1.y, a1.z, a1.w};
            float b[4] = {bv.x, bv.y, bv.z, bv.w};
#pragma unroll
            for (int i = 0; i < 8; i++)
#pragma unroll
                for (int j = 0; j < 4; j++) acc[i][j] += a[i] * b[j];
        }
        __syncthreads();
    }
#pragma unroll
    for (int i = 0; i < 8; i++) {
        int m = m0 + ty * 8 + i;
        int b = m >> 10, t = m & 1023;
        float4 o = make_float4(acc[i][0], acc[i][1], acc[i][2], acc[i][3]);
        *(float4*)&out[((size_t)(b * NH + h) * NT + t) * NDK + tx * 4] = o;
    }
}

// ---------------------------------------------------------------------------
// Kernel 2: biasQ[row, r] = sum_d qW[row,d] * emb_Q[r,d]   (row = bh*T+t)
// ---------------------------------------------------------------------------
__global__ void __launch_bounds__(256) biasq_kernel(const float* __restrict__ embQ)
{
    __shared__ float qs[64][64];
    __shared__ float eq[NR][NR];   // padded stride 65 -> conflict-free
    const int tid  = threadIdx.x;
    const int row0 = blockIdx.x * 64;

#pragma unroll
    for (int it = 0; it < 4; it++) {
        int f = tid + it * 256;                 // 1024 float4 = 64x64
        int r = f >> 4, dq = (f & 15) << 2;
        *(float4*)&qs[r][dq] = *(const float4*)&g_qW[(size_t)(row0 + r) * NDK + dq];
    }
    for (int f = tid; f < NR * NDK; f += 256)
        eq[f >> 6][f & 63] = embQ[f];
    __syncthreads();

    for (int o = tid; o < 64 * NR; o += 256) {
        int r = o / NR;
        int c = o - r * NR;
        float s = 0.f;
#pragma unroll
        for (int d = 0; d < NDK; d++) s += qs[r][d] * eq[c][d];
        g_biasQ[(size_t)(row0 + r) * NR + c] = s;
    }
}

// ---------------------------------------------------------------------------
// Kernel 3: scores  P[bh,t,s] = (qW[t]·kW[s] + biasQ[t, rel(s-t)]) / 8
// BM=128 (t), BN=64 (s), K=64 in two 32-chunks.
// ---------------------------------------------------------------------------
__global__ void __launch_bounds__(256) scores_kernel()
{
    __shared__ float Qs[32][128];
    __shared__ float Ks[32][64];
    const int tid = threadIdx.x;
    const int s0  = blockIdx.x * 64;
    const int t0  = blockIdx.y * 128;
    const int bh  = blockIdx.z;
    const float* Qg = g_qW + (size_t)bh * NT * NDK;
    const float* Kg = g_kW + (size_t)bh * NT * NDK;
    const int ty = tid >> 4, tx = tid & 15;

    float acc[8][4];
#pragma unroll
    for (int i = 0; i < 8; i++)
#pragma unroll
        for (int j = 0; j < 4; j++) acc[i][j] = 0.f;

    for (int kc = 0; kc < NDK; kc += 32) {
#pragma unroll
        for (int it = 0; it < 4; it++) {
            int f = tid + it * 256;             // 1024 f4 = 128 rows x 8
            int r = f >> 3, dq = (f & 7) << 2;
            float4 v = *(const float4*)&Qg[(size_t)(t0 + r) * NDK + kc + dq];
            Qs[dq + 0][r] = v.x; Qs[dq + 1][r] = v.y;
            Qs[dq + 2][r] = v.z; Qs[dq + 3][r] = v.w;
        }
#pragma unroll
        for (int it = 0; it < 2; it++) {
            int f = tid + it * 256;             // 512 f4 = 64 rows x 8
            int r = f >> 3, dq = (f & 7) << 2;
            float4 v = *(const float4*)&Kg[(size_t)(s0 + r) * NDK + kc + dq];
            Ks[dq + 0][r] = v.x; Ks[dq + 1][r] = v.y;
            Ks[dq + 2][r] = v.z; Ks[dq + 3][r] = v.w;
        }
        __syncthreads();
#pragma unroll
        for (int kk = 0; kk < 32; kk++) {
            float4 a0 = *(const float4*)&Qs[kk][ty * 8];
            float4 a1 = *(const float4*)&Qs[kk][ty * 8 + 4];
            float4 bv = *(const float4*)&Ks[kk][tx * 4];
            float a[8] = {a0.x, a0.y, a0.z, a0.w, a1.x, a1.y, a1.z, a1.w};
            float b[4] = {bv.x, bv.y, bv.z, bv.w};
#pragma unroll
            for (int i = 0; i < 8; i++)
#pragma unroll
                for (int j = 0; j < 4; j++) acc[i][j] += a[i] * b[j];
        }
        __syncthreads();
    }

    const float* biasB = g_biasQ + (size_t)bh * NT * NR;
#pragma unroll
    for (int i = 0; i < 8; i++) {
        int t = t0 + ty * 8 + i;
        const float* br = biasB + (size_t)t * NR;
        int sb = s0 + tx * 4;
        float4 o;
        o.x = (acc[i][0] + br[relidx(sb + 0 - t)]) * 0.125f;
        o.y = (acc[i][1] + br[relidx(sb + 1 - t)]) * 0.125f;
        o.z = (acc[i][2] + br[relidx(sb + 2 - t)]) * 0.125f;
        o.w = (acc[i][3] + br[relidx(sb + 3 - t)]) * 0.125f;
        *(float4*)&g_P[((size_t)bh * NT + t) * NT + sb] = o;
    }
}

// ---------------------------------------------------------------------------
// Kernel 4: row softmax (in place on g_P) + 65-bucket rel sums +
//           rel-value head:  g_heads[row,d] = sum_r bucket[r] * emb_S[r,d]
// One block per row (bh*T+t), 256 threads x 4 elements.
// ---------------------------------------------------------------------------
__global__ void __launch_bounds__(256) softmax_kernel(const float* __restrict__ embS)
{
    const int row = blockIdx.x;
    const int t   = row & (NT - 1);
    float* p      = g_P + (size_t)row * NT;
    const int tid = threadIdx.x;

    __shared__ float bk[NR];
    __shared__ float red[8];
    __shared__ float stat[2];
    if (tid < NR) bk[tid] = 0.f;

    float4 v = ((const float4*)p)[tid];
    float mx = fmaxf(fmaxf(v.x, v.y), fmaxf(v.z, v.w));
#pragma unroll
    for (int off = 16; off > 0; off >>= 1)
        mx = fmaxf(mx, __shfl_xor_sync(0xffffffffu, mx, off));
    if ((tid & 31) == 0) red[tid >> 5] = mx;
    __syncthreads();
    if (tid == 0) {
        float m = red[0];
#pragma unroll
        for (int w = 1; w < 8; w++) m = fmaxf(m, red[w]);
        stat[0] = m;
    }
    __syncthreads();
    mx = stat[0];

    float4 e;
    e.x = __expf(v.x - mx); e.y = __expf(v.y - mx);
    e.z = __expf(v.z - mx); e.w = __expf(v.w - mx);
    float ss = e.x + e.y + e.z + e.w;
#pragma unroll
    for (int off = 16; off > 0; off >>= 1)
        ss += __shfl_xor_sync(0xffffffffu, ss, off);
    if ((tid & 31) == 0) red[tid >> 5] = ss;
    __syncthreads();
    if (tid == 0) {
        float s = 0.f;
#pragma unroll
        for (int w = 0; w < 8; w++) s += red[w];
        stat[1] = 1.0f / s;
    }
    __syncthreads();
    const float inv = stat[1];
    e.x *= inv; e.y *= inv; e.z *= inv; e.w *= inv;
    ((float4*)p)[tid] = e;

    // bucket accumulation (normalized probs)
    int sb = tid * 4;
    float s4 = e.x + e.y + e.z + e.w;
    if (sb + 3 - t <= -32) {
        atomicAdd(&bk[0], s4);
    } else if (sb - t >= 32) {
        atomicAdd(&bk[64], s4);
    } else {
        atomicAdd(&bk[relidx(sb + 0 - t)], e.x);
        atomicAdd(&bk[relidx(sb + 1 - t)], e.y);
        atomicAdd(&bk[relidx(sb + 2 - t)], e.z);
        atomicAdd(&bk[relidx(sb + 3 - t)], e.w);
    }
    __syncthreads();

    if (tid < NDK) {
        float hv = 0.f;
#pragma unroll
        for (int r = 0; r < NR; r++) hv += bk[r] * embS[r * NDK + tid];
        g_heads[(size_t)row * NDK + tid] = hv;
    }
}

// ---------------------------------------------------------------------------
// Kernel 5: PV  g_heads[bh,t,d] += sum_s P[bh,t,s] * vW[bh,s,d]
// BM=128 (t), N=64 (full Dk), K=1024 in 32-chunks.
// ---------------------------------------------------------------------------
__global__ void __launch_bounds__(256) pv_kernel()
{
    __shared__ float Ps[32][128];
    __shared__ float Vs[32][64];
    const int tid = threadIdx.x;
    const int t0  = blockIdx.y * 128;
    const int bh  = blockIdx.z;
    const float* Pg = g_P + ((size_t)bh * NT + t0) * NT;
    const float* Vg = g_vW + (size_t)bh * NT * NDK;
    const int ty = tid >> 4, tx = tid & 15;

    float acc[8][4];
#pragma unroll
    for (int i = 0; i < 8; i++)
#pragma unroll
        for (int j = 0; j < 4; j++) acc[i][j] = 0.f;

    for (int k0 = 0; k0 < NT; k0 += 32) {
#pragma unroll
        for (int it = 0; it < 4; it++) {
            int f = tid + it * 256;             // 1024 f4 = 128 rows x 8
            int r = f >> 3, sq = (f & 7) << 2;
            float4 v = *(const float4*)&Pg[(size_t)r * NT + k0 + sq];
            Ps[sq + 0][r] = v.x; Ps[sq + 1][r] = v.y;
            Ps[sq + 2][r] = v.z; Ps[sq + 3][r] = v.w;
        }
#pragma unroll
        for (int it = 0; it < 2; it++) {
            int f = tid + it * 256;             // 512 f4 = 32 rows x 16
            int r = f >> 4, dq = (f & 15) << 2;
            *(float4*)&Vs[r][dq] = *(const float4*)&Vg[(size_t)(k0 + r) * NDK + dq];
        }
        __syncthreads();
#pragma unroll
        for (int kk = 0; kk < 32; kk++) {
            float4 a0 = *(const float4*)&Ps[kk][ty * 8];
            float4 a1 = *(const float4*)&Ps[kk][ty * 8 + 4];
            float4 bv = *(const float4*)&Vs[kk][tx * 4];
            float a[8] = {a0.x, a0.y, a0.z, a0.w, a1.x, a1.y, a1.z, a1.w};
            float b[4] = {bv.x, bv.y, bv.z, bv.w};
#pragma unroll
            for (int i = 0; i < 8; i++)
#pragma unroll
                for (int j = 0; j < 4; j++) acc[i][j] += a[i] * b[j];
        }
        __syncthreads();
    }
#pragma unroll
    for (int i = 0; i < 8; i++) {
        size_t idx = ((size_t)bh * NT + t0 + ty * 8 + i) * NDK + tx * 4;
        float4 hv = *(const float4*)&g_heads[idx];
        hv.x += acc[i][0]; hv.y += acc[i][1];
        hv.z += acc[i][2]; hv.w += acc[i][3];
        *(float4*)&g_heads[idx] = hv;
    }
}

// ---------------------------------------------------------------------------
// Kernel 6: output projection out[b,t,m] = sum_{h,d} heads[b,h,t,d] W_O[h,d,m]
// W_O flat == (1024,1024) row-major with k = h*64+d. BM=128,BN=64,BK=16.
// ---------------------------------------------------------------------------
__global__ void __launch_bounds__(256) outproj_gemm(const float* __restrict__ WO,
                                                    float* __restrict__ out)
{
    __shared__ float As[16][128];
    __shared__ float Bs[16][64];
    const int tid = threadIdx.x;
    const int m0  = blockIdx.y * 128;
    const int n0  = blockIdx.x * 64;
    const int ty  = tid >> 4, tx = tid & 15;
    const int lr  = tid >> 2;
    const int lkq = (tid & 3) << 2;
    const int bkk = tid >> 4;
    const int bkd = (tid & 15) << 2;

    float acc[8][4];
#pragma unroll
    for (int i = 0; i < 8; i++)
#pragma unroll
        for (int j = 0; j < 4; j++) acc[i][j] = 0.f;

    for (int k0 = 0; k0 < NDM; k0 += 16) {
        const int h  = k0 >> 6;
        const int d0 = (k0 & 63) + lkq;
#pragma unroll
        for (int rr = 0; rr < 128; rr += 64) {
            int m = m0 + lr + rr;
            int b = m >> 10, t = m & 1023;
            float4 v = *(const float4*)&g_heads[((size_t)(b * NH + h) * NT + t) * NDK + d0];
            As[lkq + 0][lr + rr] = v.x;
            As[lkq + 1][lr + rr] = v.y;
            As[lkq + 2][lr + rr] = v.z;
            As[lkq + 3][lr + rr] = v.w;
        }
        *(float4*)&Bs[bkk][bkd] = *(const float4*)&WO[(size_t)(k0 + bkk) * NDM + n0 + bkd];
        __syncthreads();
#pragma unroll
        for (int kk = 0; kk < 16; kk++) {
            float4 a0 = *(const float4*)&As[kk][ty * 8];
            float4 a1 = *(const float4*)&As[kk][ty * 8 + 4];
            float4 bv = *(const float4*)&Bs[kk][tx * 4];
            float a[8] = {a0.x, a0.y, a0.z, a0.w, a1.x, a1.y, a1.z, a1.w};
            float b[4] = {bv.x, bv.y, bv.z, bv.w};
#pragma unroll
            for (int i = 0; i < 8; i++)
#pragma unroll
                for (int j = 0; j < 4; j++) acc[i][j] += a[i] * b[j];
        }
        __syncthreads();
    }
#pragma unroll
    for (int i = 0; i < 8; i++) {
        int m = m0 + ty * 8 + i;
        float4 o = make_float4(acc[i][0], acc[i][1], acc[i][2], acc[i][3]);
        *(float4*)&out[(size_t)m * NDM + n0 + tx * 4] = o;
    }
}

// ---------------------------------------------------------------------------
// Launch
// ---------------------------------------------------------------------------
extern "C" void kernel_launch(void* const* d_in, const int* in_sizes, int n_in,
                              void* d_out, int out_size)
{
    const float* query = (const float*)d_in[0];
    const float* value = (const float*)d_in[1];
    const float* W_Q   = (const float*)d_in[2];
    const float* W_K   = (const float*)d_in[3];
    const float* W_V   = (const float*)d_in[4];
    const float* W_O   = (const float*)d_in[5];
    const float* emb_Q = (const float*)d_in[6];
    const float* emb_S = (const float*)d_in[7];
    float* out = (float*)d_out;

    dim3 pg(NH, (NB * NT) / 128);                       // (16, 32)
    proj_gemm<0><<<pg, 256>>>(query, W_Q);
    proj_gemm<1><<<pg, 256>>>(value, W_K);
    proj_gemm<2><<<pg, 256>>>(value, W_V);

    biasq_kernel<<<(NBH * NT) / 64, 256>>>(emb_Q);

    scores_kernel<<<dim3(NT / 64, NT / 128, NBH), 256>>>();

    softmax_kernel<<<NBH * NT, 256>>>(emb_S);

    pv_kernel<<<dim3(1, NT / 128, NBH), 256>>>();

    outproj_gemm<<<dim3(NDM / 64, (NB * NT) / 128), 256>>>(W_O, out);
}

// round 2
// speedup vs baseline: 1.0008x; 1.0008x over previous
#include <cuda_runtime.h>

// Problem dims
#define NB   4
#define NT   1024
#define NDM  1024
#define NH   16
#define NDK  64
#define NR   65      // 2*CLIP+1
#define NBH  64      // NB*NH

// ---------------------------------------------------------------------------
// Device scratch (allocation-free: static __device__ arrays)
// ---------------------------------------------------------------------------
__device__ __align__(16) float g_qW[NB * NH * NT * NDK];       // (B,H,T,Dk)
__device__ __align__(16) float g_kW[NB * NH * NT * NDK];
__device__ __align__(16) float g_vW[NB * NH * NT * NDK];
__device__ __align__(16) float g_biasQ[NB * NH * NT * NR];     // (B,H,T,65)
__device__ __align__(16) float g_heads[NB * NH * NT * NDK];    // (B,H,T,Dk)
__device__ __align__(16) float g_P[(size_t)NBH * NT * NT];     // (BH,T,T) probs

__device__ __forceinline__ int relidx(int delta) {
    delta = delta < -32 ? -32 : delta;
    delta = delta >  32 ?  32 : delta;
    return delta + 32;
}

// ---------------------------------------------------------------------------
// Kernel 1: projections  qW/kW/vW[b,h,t,d] = sum_m X[b,t,m] * W[h,m,d]
// Tiled SGEMM: M=4096 (b,t), N=64 per block (one head h), K=1024. BM=128,BN=64,BK=16.
// ---------------------------------------------------------------------------
template <int SEL>
__global__ void __launch_bounds__(256) proj_gemm(const float* __restrict__ X,
                                                 const float* __restrict__ W)
{
    __shared__ float As[16][128];
    __shared__ float Bs[16][64];
    float* out = (SEL == 0) ? g_qW : (SEL == 1) ? g_kW : g_vW;

    const int tid = threadIdx.x;
    const int m0  = blockIdx.y * 128;
    const int h   = blockIdx.x;                 // N-tile == one head
    const float* Wh = W + (size_t)h * NDM * NDK;

    const int ty  = tid >> 4, tx = tid & 15;
    const int lr  = tid >> 2;                   // A-load row 0..63
    const int lkq = (tid & 3) << 2;             // A-load k quad
    const int bkk = tid >> 4;                   // B-load k 0..15
    const int bkd = (tid & 15) << 2;            // B-load d quad

    float acc[8][4];
#pragma unroll
    for (int i = 0; i < 8; i++)
#pragma unroll
        for (int j = 0; j < 4; j++) acc[i][j] = 0.f;

    for (int k0 = 0; k0 < NDM; k0 += 16) {
#pragma unroll
        for (int rr = 0; rr < 128; rr += 64) {
            float4 v = *(const float4*)&X[(size_t)(m0 + lr + rr) * NDM + k0 + lkq];
            As[lkq + 0][lr + rr] = v.x;
            As[lkq + 1][lr + rr] = v.y;
            As[lkq + 2][lr + rr] = v.z;
            As[lkq + 3][lr + rr] = v.w;
        }
        *(float4*)&Bs[bkk][bkd] = *(const float4*)&Wh[(size_t)(k0 + bkk) * NDK + bkd];
        __syncthreads();
#pragma unroll
        for (int kk = 0; kk < 16; kk++) {
            float4 a0 = *(const float4*)&As[kk][ty * 8];
            float4 a1 = *(const float4*)&As[kk][ty * 8 + 4];
            float4 bv = *(const float4*)&Bs[kk][tx * 4];
            float a[8] = {a0.x, a0.y, a0.z, a0.w, a1.x, a1.y, a1.z, a1.w};
            float b[4] = {bv.x, bv.y, bv.z, bv.w};
#pragma unroll
            for (int i = 0; i < 8; i++)
#pragma unroll
                for (int j = 0; j < 4; j++) acc[i][j] += a[i] * b[j];
        }
        __syncthreads();
    }
#pragma unroll
    for (int i = 0; i < 8; i++) {
        int m = m0 + ty * 8 + i;
        int b = m >> 10, t = m & 1023;
        float4 o = make_float4(acc[i][0], acc[i][1], acc[i][2], acc[i][3]);
        *(float4*)&out[((size_t)(b * NH + h) * NT + t) * NDK + tx * 4] = o;
    }
}

// ---------------------------------------------------------------------------
// Kernel 2: biasQ[row, r] = sum_d qW[row,d] * emb_Q[r,d]   (row = bh*T+t)
// ---------------------------------------------------------------------------
__global__ void __launch_bounds__(256) biasq_kernel(const float* __restrict__ embQ)
{
    __shared__ float qs[64][64];
    __shared__ float eq[NR][NR];   // padded stride 65 -> conflict-free
    const int tid  = threadIdx.x;
    const int row0 = blockIdx.x * 64;

#pragma unroll
    for (int it = 0; it < 4; it++) {
        int f = tid + it * 256;                 // 1024 float4 = 64x64
        int r = f >> 4, dq = (f & 15) << 2;
        *(float4*)&qs[r][dq] = *(const float4*)&g_qW[(size_t)(row0 + r) * NDK + dq];
    }
    for (int f = tid; f < NR * NDK; f += 256)
        eq[f >> 6][f & 63] = embQ[f];
    __syncthreads();

    for (int o = tid; o < 64 * NR; o += 256) {
        int r = o / NR;
        int c = o - r * NR;
        float s = 0.f;
#pragma unroll
        for (int d = 0; d < NDK; d++) s += qs[r][d] * eq[c][d];
        g_biasQ[(size_t)(row0 + r) * NR + c] = s;
    }
}

// ---------------------------------------------------------------------------
// Kernel 3: scores  P[bh,t,s] = (qW[t]·kW[s] + biasQ[t, rel(s-t)]) / 8
// BM=128 (t), BN=64 (s), K=64 in two 32-chunks.
// ---------------------------------------------------------------------------
__global__ void __launch_bounds__(256) scores_kernel()
{
    __shared__ float Qs[32][128];
    __shared__ float Ks[32][64];
    const int tid = threadIdx.x;
    const int s0  = blockIdx.x * 64;
    const int t0  = blockIdx.y * 128;
    const int bh  = blockIdx.z;
    const float* Qg = g_qW + (size_t)bh * NT * NDK;
    const float* Kg = g_kW + (size_t)bh * NT * NDK;
    const int ty = tid >> 4, tx = tid & 15;

    float acc[8][4];
#pragma unroll
    for (int i = 0; i < 8; i++)
#pragma unroll
        for (int j = 0; j < 4; j++) acc[i][j] = 0.f;

    for (int kc = 0; kc < NDK; kc += 32) {
#pragma unroll
        for (int it = 0; it < 4; it++) {
            int f = tid + it * 256;             // 1024 f4 = 128 rows x 8
            int r = f >> 3, dq = (f & 7) << 2;
            float4 v = *(const float4*)&Qg[(size_t)(t0 + r) * NDK + kc + dq];
            Qs[dq + 0][r] = v.x; Qs[dq + 1][r] = v.y;
            Qs[dq + 2][r] = v.z; Qs[dq + 3][r] = v.w;
        }
#pragma unroll
        for (int it = 0; it < 2; it++) {
            int f = tid + it * 256;             // 512 f4 = 64 rows x 8
            int r = f >> 3, dq = (f & 7) << 2;
            float4 v = *(const float4*)&Kg[(size_t)(s0 + r) * NDK + kc + dq];
            Ks[dq + 0][r] = v.x; Ks[dq + 1][r] = v.y;
            Ks[dq + 2][r] = v.z; Ks[dq + 3][r] = v.w;
        }
        __syncthreads();
#pragma unroll
        for (int kk = 0; kk < 32; kk++) {
            float4 a0 = *(const float4*)&Qs[kk][ty * 8];
            float4 a1 = *(const float4*)&Qs[kk][ty * 8 + 4];
            float4 bv = *(const float4*)&Ks[kk][tx * 4];
            float a[8] = {a0.x, a0.y, a0.z, a0.w, a1.x, a1.y, a1.z, a1.w};
            float b[4] = {bv.x, bv.y, bv.z, bv.w};
#pragma unroll
            for (int i = 0; i < 8; i++)
#pragma unroll
                for (int j = 0; j < 4; j++) acc[i][j] += a[i] * b[j];
        }
        __syncthreads();
    }

    const float* biasB = g_biasQ + (size_t)bh * NT * NR;
#pragma unroll
    for (int i = 0; i < 8; i++) {
        int t = t0 + ty * 8 + i;
        const float* br = biasB + (size_t)t * NR;
        int sb = s0 + tx * 4;
        float4 o;
        o.x = (acc[i][0] + br[relidx(sb + 0 - t)]) * 0.125f;
        o.y = (acc[i][1] + br[relidx(sb + 1 - t)]) * 0.125f;
        o.z = (acc[i][2] + br[relidx(sb + 2 - t)]) * 0.125f;
        o.w = (acc[i][3] + br[relidx(sb + 3 - t)]) * 0.125f;
        *(float4*)&g_P[((size_t)bh * NT + t) * NT + sb] = o;
    }
}

// ---------------------------------------------------------------------------
// Kernel 4: row softmax (in place on g_P) + 65-bucket rel sums +
//           rel-value head:  g_heads[row,d] = sum_r bucket[r] * emb_S[r,d]
// One block per row (bh*T+t), 256 threads x 4 elements.
// ---------------------------------------------------------------------------
__global__ void __launch_bounds__(256) softmax_kernel(const float* __restrict__ embS)
{
    const int row = blockIdx.x;
    const int t   = row & (NT - 1);
    float* p      = g_P + (size_t)row * NT;
    const int tid = threadIdx.x;

    __shared__ float bk[NR];
    __shared__ float red[8];
    __shared__ float stat[2];
    if (tid < NR) bk[tid] = 0.f;

    float4 v = ((const float4*)p)[tid];
    float mx = fmaxf(fmaxf(v.x, v.y), fmaxf(v.z, v.w));
#pragma unroll
    for (int off = 16; off > 0; off >>= 1)
        mx = fmaxf(mx, __shfl_xor_sync(0xffffffffu, mx, off));
    if ((tid & 31) == 0) red[tid >> 5] = mx;
    __syncthreads();
    if (tid == 0) {
        float m = red[0];
#pragma unroll
        for (int w = 1; w < 8; w++) m = fmaxf(m, red[w]);
        stat[0] = m;
    }
    __syncthreads();
    mx = stat[0];

    float4 e;
    e.x = __expf(v.x - mx); e.y = __expf(v.y - mx);
    e.z = __expf(v.z - mx); e.w = __expf(v.w - mx);
    float ss = e.x + e.y + e.z + e.w;
#pragma unroll
    for (int off = 16; off > 0; off >>= 1)
        ss += __shfl_xor_sync(0xffffffffu, ss, off);
    if ((tid & 31) == 0) red[tid >> 5] = ss;
    __syncthreads();
    if (tid == 0) {
        float s = 0.f;
#pragma unroll
        for (int w = 0; w < 8; w++) s += red[w];
        stat[1] = 1.0f / s;
    }
    __syncthreads();
    const float inv = stat[1];
    e.x *= inv; e.y *= inv; e.z *= inv; e.w *= inv;
    ((float4*)p)[tid] = e;

    // bucket accumulation (normalized probs)
    int sb = tid * 4;
    float s4 = e.x + e.y + e.z + e.w;
    if (sb + 3 - t <= -32) {
        atomicAdd(&bk[0], s4);
    } else if (sb - t >= 32) {
        atomicAdd(&bk[64], s4);
    } else {
        atomicAdd(&bk[relidx(sb + 0 - t)], e.x);
        atomicAdd(&bk[relidx(sb + 1 - t)], e.y);
        atomicAdd(&bk[relidx(sb + 2 - t)], e.z);
        atomicAdd(&bk[relidx(sb + 3 - t)], e.w);
    }
    __syncthreads();

    if (tid < NDK) {
        float hv = 0.f;
#pragma unroll
        for (int r = 0; r < NR; r++) hv += bk[r] * embS[r * NDK + tid];
        g_heads[(size_t)row * NDK + tid] = hv;
    }
}

// ---------------------------------------------------------------------------
// Kernel 5: PV  g_heads[bh,t,d] += sum_s P[bh,t,s] * vW[bh,s,d]
// BM=128 (t), N=64 (full Dk), K=1024 in 32-chunks.
// ---------------------------------------------------------------------------
__global__ void __launch_bounds__(256) pv_kernel()
{
    __shared__ float Ps[32][128];
    __shared__ float Vs[32][64];
    const int tid = threadIdx.x;
    const int t0  = blockIdx.y * 128;
    const int bh  = blockIdx.z;
    const float* Pg = g_P + ((size_t)bh * NT + t0) * NT;
    const float* Vg = g_vW + (size_t)bh * NT * NDK;
    const int ty = tid >> 4, tx = tid & 15;

    float acc[8][4];
#pragma unroll
    for (int i = 0; i < 8; i++)
#pragma unroll
        for (int j = 0; j < 4; j++) acc[i][j] = 0.f;

    for (int k0 = 0; k0 < NT; k0 += 32) {
#pragma unroll
        for (int it = 0; it < 4; it++) {
            int f = tid + it * 256;             // 1024 f4 = 128 rows x 8
            int r = f >> 3, sq = (f & 7) << 2;
            float4 v = *(const float4*)&Pg[(size_t)r * NT + k0 + sq];
            Ps[sq + 0][r] = v.x; Ps[sq + 1][r] = v.y;
            Ps[sq + 2][r] = v.z; Ps[sq + 3][r] = v.w;
        }
#pragma unroll
        for (int it = 0; it < 2; it++) {
            int f = tid + it * 256;             // 512 f4 = 32 rows x 16
            int r = f >> 4, dq = (f & 15) << 2;
            *(float4*)&Vs[r][dq] = *(const float4*)&Vg[(size_t)(k0 + r) * NDK + dq];
        }
        __syncthreads();
#pragma unroll
        for (int kk = 0; kk < 32; kk++) {
            float4 a0 = *(const float4*)&Ps[kk][ty * 8];
            float4 a1 = *(const float4*)&Ps[kk][ty * 8 + 4];
            float4 bv = *(const float4*)&Vs[kk][tx * 4];
            float a[8] = {a0.x, a0.y, a0.z, a0.w, a1.x, a1.y, a1.z, a1.w};
            float b[4] = {bv.x, bv.y, bv.z, bv.w};
#pragma unroll
            for (int i = 0; i < 8; i++)
#pragma unroll
                for (int j = 0; j < 4; j++) acc[i][j] += a[i] * b[j];
        }
        __syncthreads();
    }
#pragma unroll
    for (int i = 0; i < 8; i++) {
        size_t idx = ((size_t)bh * NT + t0 + ty * 8 + i) * NDK + tx * 4;
        float4 hv = *(const float4*)&g_heads[idx];
        hv.x += acc[i][0]; hv.y += acc[i][1];
        hv.z += acc[i][2]; hv.w += acc[i][3];
        *(float4*)&g_heads[idx] = hv;
    }
}

// ---------------------------------------------------------------------------
// Kernel 6: output projection out[b,t,m] = sum_{h,d} heads[b,h,t,d] W_O[h,d,m]
// W_O flat == (1024,1024) row-major with k = h*64+d. BM=128,BN=64,BK=16.
// ---------------------------------------------------------------------------
__global__ void __launch_bounds__(256) outproj_gemm(const float* __restrict__ WO,
                                                    float* __restrict__ out)
{
    __shared__ float As[16][128];
    __shared__ float Bs[16][64];
    const int tid = threadIdx.x;
    const int m0  = blockIdx.y * 128;
    const int n0  = blockIdx.x * 64;
    const int ty  = tid >> 4, tx = tid & 15;
    const int lr  = tid >> 2;
    const int lkq = (tid & 3) << 2;
    const int bkk = tid >> 4;
    const int bkd = (tid & 15) << 2;

    float acc[8][4];
#pragma unroll
    for (int i = 0; i < 8; i++)
#pragma unroll
        for (int j = 0; j < 4; j++) acc[i][j] = 0.f;

    for (int k0 = 0; k0 < NDM; k0 += 16) {
        const int h  = k0 >> 6;
        const int d0 = (k0 & 63) + lkq;
#pragma unroll
        for (int rr = 0; rr < 128; rr += 64) {
            int m = m0 + lr + rr;
            int b = m >> 10, t = m & 1023;
            float4 v = *(const float4*)&g_heads[((size_t)(b * NH + h) * NT + t) * NDK + d0];
            As[lkq + 0][lr + rr] = v.x;
            As[lkq + 1][lr + rr] = v.y;
            As[lkq + 2][lr + rr] = v.z;
            As[lkq + 3][lr + rr] = v.w;
        }
        *(float4*)&Bs[bkk][bkd] = *(const float4*)&WO[(size_t)(k0 + bkk) * NDM + n0 + bkd];
        __syncthreads();
#pragma unroll
        for (int kk = 0; kk < 16; kk++) {
            float4 a0 = *(const float4*)&As[kk][ty * 8];
            float4 a1 = *(const float4*)&As[kk][ty * 8 + 4];
            float4 bv = *(const float4*)&Bs[kk][tx * 4];
            float a[8] = {a0.x, a0.y, a0.z, a0.w, a1.x, a1.y, a1.z, a1.w};
            float b[4] = {bv.x, bv.y, bv.z, bv.w};
#pragma unroll
            for (int i = 0; i < 8; i++)
#pragma unroll
                for (int j = 0; j < 4; j++) acc[i][j] += a[i] * b[j];
        }
        __syncthreads();
    }
#pragma unroll
    for (int i = 0; i < 8; i++) {
        int m = m0 + ty * 8 + i;
        float4 o = make_float4(acc[i][0], acc[i][1], acc[i][2], acc[i][3]);
        *(float4*)&out[(size_t)m * NDM + n0 + tx * 4] = o;
    }
}

// ---------------------------------------------------------------------------
// Launch
// ---------------------------------------------------------------------------
extern "C" void kernel_launch(void* const* d_in, const int* in_sizes, int n_in,
                              void* d_out, int out_size)
{
    const float* query = (const float*)d_in[0];
    const float* value = (const float*)d_in[1];
    const float* W_Q   = (const float*)d_in[2];
    const float* W_K   = (const float*)d_in[3];
    const float* W_V   = (const float*)d_in[4];
    const float* W_O   = (const float*)d_in[5];
    const float* emb_Q = (const float*)d_in[6];
    const float* emb_S = (const float*)d_in[7];
    float* out = (float*)d_out;

    dim3 pg(NH, (NB * NT) / 128);                       // (16, 32)
    proj_gemm<0><<<pg, 256>>>(query, W_Q);
    proj_gemm<1><<<pg, 256>>>(value, W_K);
    proj_gemm<2><<<pg, 256>>>(value, W_V);

    biasq_kernel<<<(NBH * NT) / 64, 256>>>(emb_Q);

    scores_kernel<<<dim3(NT / 64, NT / 128, NBH), 256>>>();

    softmax_kernel<<<NBH * NT, 256>>>(emb_S);

    pv_kernel<<<dim3(1, NT / 128, NBH), 256>>>();

    outproj_gemm<<<dim3(NDM / 64, (NB * NT) / 128), 256>>>(W_O, out);
}